// round 2
// baseline (speedup 1.0000x reference)
#include <cuda_runtime.h>
#include <cstdint>

#define B_ 64
#define I_ 64
#define O_ 64
#define T_ 8192
#define KW 3
#define KDIM 192      // I_*KW
#define NH 64
#define MW 32
#define QD 320

#define TT 256
#define XS 264        // padded x tile row stride (floats): 264 % 32 == 8 -> conflict-free rows
#define AS 196        // padded A row stride (floats): 196 % 32 == 4 -> conflict-free frag loads
#define CONV_THREADS 256
#define CONV_GRID 152
#define TILES_TOTAL (B_*(T_/TT))   // 2048
#define SMEM_FLOATS (O_*AS + 64 + 2*I_*XS)   // 12544 + 64 + 33792 = 46400
#define SMEM_BYTES (SMEM_FLOATS*4)           // 185600

// -------------------- device scratch (no allocations allowed) --------------------
__device__ __align__(16) float g_rep[O_*NH];
__device__ __align__(16) float g_cw[O_*KDIM];   // tf32-rounded effective weights [o][i*3+k]
__device__ __align__(16) float g_bias[O_];

__device__ __forceinline__ float sigmoidf_(float x){ return 1.f/(1.f+expf(-x)); }
__device__ __forceinline__ float siluf_(float x){ return x * sigmoidf_(x); }
__device__ __forceinline__ uint32_t f2tf32(float x){
  uint32_t r; asm("cvt.rna.tf32.f32 %0, %1;" : "=r"(r) : "f"(x)); return r;
}

// -------------------- prep kernel 1: rep = silu(g @ ctrl_w.T + ctrl_b) --------------------
__global__ void prep_rep_kernel(const float* __restrict__ grads,
                                const float* __restrict__ ctrl_w,
                                const float* __restrict__ ctrl_b) {
  int o = blockIdx.x;          // 64 blocks
  int h = threadIdx.x;         // 64 threads
  const float* g = grads + o*KDIM;
  const float* w = ctrl_w + h*KDIM;
  float s = ctrl_b[h];
  #pragma unroll 4
  for (int j = 0; j < KDIM; ++j) s += g[j]*w[j];
  g_rep[o*NH + h] = siluf_(s);
}

// -------------------- prep kernel 2: heads, tau, EMA, trigger branch, emit cw_eff/bias --------------------
__global__ void prep_q_kernel(const float* __restrict__ q_ema, const float* __restrict__ W,
    const float* __restrict__ conv_w, const float* __restrict__ conv_b,
    const float* __restrict__ cw_w, const float* __restrict__ cw_b,
    const float* __restrict__ cb_w, const float* __restrict__ cb_b,
    const float* __restrict__ cf_w, const float* __restrict__ cf_b,
    const float* __restrict__ tau_w1, const float* __restrict__ tau_b1,
    const float* __restrict__ tau_w2, const float* __restrict__ tau_b2,
    const int* __restrict__ trigger)
{
  __shared__ float s_rep[O_*NH];
  __shared__ float s_q[QD];
  __shared__ float s_red[O_];
  __shared__ float s_tau;
  __shared__ float s_att[MW];
  __shared__ int   s_idx[3];
  __shared__ float s_v[3];
  int tid = threadIdx.x;       // 384 threads

  for (int i = tid; i < O_*NH; i += 384) s_rep[i] = g_rep[i];
  __syncthreads();

  // q entries: w (192), b (64), f (64)
  if (tid < 192) {
    int o = tid/3, k = tid - 3*(tid/3);
    const float* r = s_rep + o*NH;
    const float* w = cw_w + k*NH;
    float s = cw_b[k];
    for (int h = 0; h < NH; ++h) s += r[h]*w[h];
    s_q[o*3+k] = s;
  } else if (tid < 256) {
    int o = tid - 192;
    const float* r = s_rep + o*NH;
    float s = cb_b[0];
    for (int h = 0; h < NH; ++h) s += r[h]*cb_w[h];
    s_q[192+o] = s;
  } else if (tid < 320) {
    int o = tid - 256;
    const float* r = s_rep + o*NH;
    float s = cf_b[0];
    for (int h = 0; h < NH; ++h) s += r[h]*cf_w[h];
    s_q[256+o] = s;
  }
  // tau path (additional work for tid<64)
  if (tid < O_) {
    const float* r = s_rep + tid*NH;
    float acc = tau_b2[0];
    for (int j = 0; j < 16; ++j) {
      float s = tau_b1[j];
      const float* w = tau_w1 + j*NH;
      for (int h = 0; h < NH; ++h) s += r[h]*w[h];
      acc += siluf_(s)*tau_w2[j];
    }
    s_red[tid] = sigmoidf_(acc);
  }
  __syncthreads();
  if (tid == 0) {
    float m = 0.f;
    for (int o = 0; o < O_; ++o) m += s_red[o];
    s_tau = (m * (1.f/64.f))*0.5f + 0.5f;
  }
  __syncthreads();

  // EMA mix: q = 0.5*q + 0.5*(0.3*q_ema + 0.7*q) = 0.85*q + 0.15*q_ema
  if (tid < QD) s_q[tid] = 0.85f*s_q[tid] + 0.15f*q_ema[tid];
  __syncthreads();

  int trig = trigger[0];
  if (trig == 1) {
    if (tid < MW) {
      float s = 0.f;
      for (int d = 0; d < QD; ++d) s += s_q[d]*W[d*MW + tid];
      s_att[tid] = s*2.0f;   // / TEMP (0.5)
    }
    __syncthreads();
    if (tid == 0) {
      float mx = s_att[0];
      for (int m = 1; m < MW; ++m) mx = fmaxf(mx, s_att[m]);
      float sum = 0.f;
      for (int m = 0; m < MW; ++m) { float e = expf(s_att[m]-mx); s_att[m] = e; sum += e; }
      float inv = 1.f/sum;
      for (int m = 0; m < MW; ++m) s_att[m] *= inv;
      // top-3 (strict > keeps lower index on ties, matching jax top_k)
      for (int j = 0; j < 3; ++j) {
        float best = -1e30f; int bi = 0;
        for (int m = 0; m < MW; ++m) { if (s_att[m] > best) { best = s_att[m]; bi = m; } }
        s_v[j] = best; s_idx[j] = bi; s_att[bi] = -1e30f;
      }
    }
    __syncthreads();
    float tau = s_tau;
    if (tid < QD) {
      float old = s_v[0]*W[tid*MW+s_idx[0]] + s_v[1]*W[tid*MW+s_idx[1]] + s_v[2]*W[tid*MW+s_idx[2]];
      s_q[tid] = tau*s_q[tid] + (1.f-tau)*old;
    }
    __syncthreads();
  }

  // emit effective weights / bias (fold fq gain into both)
  if (tid < O_) {
    float fq = s_q[256+tid];
    g_bias[tid] = conv_b[tid]*s_q[192+tid]*fq;   // conv_b * bq * fq (kept fp32)
  }
  for (int idx = tid; idx < O_*KDIM; idx += 384) {
    int o = idx / KDIM;
    int k = idx % 3;                 // idx = o*192 + i*3 + k, 192 % 3 == 0
    float v = conv_w[idx] * s_q[o*3+k] * s_q[256+o];
    g_cw[idx] = __uint_as_float(f2tf32(v));      // pre-round A to tf32
  }
}

// -------------------- main conv: implicit GEMM with mma.sync tf32 --------------------
__device__ __forceinline__ void prefetch_tile(const float* __restrict__ x, int ti,
                                              float* __restrict__ sXb, int tid) {
  int bb = ti >> 5;                // ti / 32
  int t0 = (ti & 31) << 8;         // tile start t
  const float* xb = x + (size_t)bb * (I_*T_);
  // 64 rows x 66 16B-chunks; window [t0-4, t0+260). Boundary chunks are fully OOB -> zeros.
  for (int c = tid; c < I_*66; c += CONV_THREADS) {
    int row = c / 66;
    int jc = c - 66*row;
    int tg = t0 - 4 + jc*4;
    float* dst = sXb + row*XS + jc*4;
    if (tg >= 0 && tg <= T_-4) {
      unsigned saddr = (unsigned)__cvta_generic_to_shared(dst);
      const float* src = xb + (size_t)row*T_ + tg;
      asm volatile("cp.async.cg.shared.global [%0], [%1], 16;" :: "r"(saddr), "l"(src));
    } else {
      *reinterpret_cast<float4*>(dst) = make_float4(0.f,0.f,0.f,0.f);
    }
  }
}

__global__ __launch_bounds__(CONV_THREADS, 1)
void conv_kernel(const float* __restrict__ x, float* __restrict__ out) {
  extern __shared__ float smem[];
  float* sA    = smem;                         // [64][196]
  float* sBias = smem + O_*AS;                 // [64]
  float* sX0   = smem + O_*AS + 64;            // [64][264]
  float* sX1   = sX0 + I_*XS;

  int tid = threadIdx.x;

  // load A (tf32-pre-rounded) into padded smem
  for (int idx = tid; idx < O_*(KDIM/4); idx += CONV_THREADS) {
    int o = idx / 48, j4 = idx - 48*o;
    float4 v = reinterpret_cast<const float4*>(g_cw)[idx];
    *reinterpret_cast<float4*>(&sA[o*AS + j4*4]) = v;
  }
  if (tid < O_) sBias[tid] = g_bias[tid];

  int start = (blockIdx.x       * TILES_TOTAL) / CONV_GRID;
  int end   = ((blockIdx.x + 1) * TILES_TOTAL) / CONV_GRID;
  if (start >= end) return;

  prefetch_tile(x, start, sX0, tid);
  asm volatile("cp.async.commit_group;");

  int wid = tid >> 5, lane = tid & 31;
  int g  = lane >> 2, t4 = lane & 3;
  int warp_m = wid & 1, warp_n = wid >> 1;
  int obase = warp_m*32 + g;
  const float* pa = sA + obase*AS + t4;
  int tloc = warp_n*64 + g + 3;     // +3: smem window starts at global t0-4, conv needs t+k-1

  for (int ti = start; ti < end; ++ti) {
    int bufc = (ti - start) & 1;
    bool more = (ti + 1 < end);
    if (more) {
      prefetch_tile(x, ti+1, bufc ? sX0 : sX1, tid);
      asm volatile("cp.async.commit_group;");
      asm volatile("cp.async.wait_group 1;");
    } else {
      asm volatile("cp.async.wait_group 0;");
    }
    __syncthreads();
    const float* sx = bufc ? sX1 : sX0;

    float c[2][8][4];
    #pragma unroll
    for (int mt = 0; mt < 2; ++mt)
      #pragma unroll
      for (int nt = 0; nt < 8; ++nt)
        { c[mt][nt][0]=0.f; c[mt][nt][1]=0.f; c[mt][nt][2]=0.f; c[mt][nt][3]=0.f; }

    #pragma unroll 1
    for (int kk = 0; kk < 24; ++kk) {
      int col = kk*8;
      uint32_t a[2][4];
      #pragma unroll
      for (int mt = 0; mt < 2; ++mt) {
        const float* paa = pa + mt*(16*AS) + col;
        a[mt][0] = __float_as_uint(paa[0]);
        a[mt][1] = __float_as_uint(paa[8*AS]);
        a[mt][2] = __float_as_uint(paa[4]);
        a[mt][3] = __float_as_uint(paa[8*AS+4]);
      }
      int ik0 = col + t4;     int i0 = ik0/3; int k0 = ik0 - i0*3;
      int ik1 = ik0 + 4;      int i1 = ik1/3; int k1 = ik1 - i1*3;
      const float* pb0 = sx + i0*XS + tloc + k0;
      const float* pb1 = sx + i1*XS + tloc + k1;
      uint32_t b0[8], b1[8];
      #pragma unroll
      for (int nt = 0; nt < 8; ++nt) {   // round-to-nearest tf32: required (truncation biases -1e-3)
        b0[nt] = f2tf32(pb0[nt*8]);
        b1[nt] = f2tf32(pb1[nt*8]);
      }
      #pragma unroll
      for (int mt = 0; mt < 2; ++mt)
        #pragma unroll
        for (int nt = 0; nt < 8; ++nt)
          asm("mma.sync.aligned.m16n8k8.row.col.f32.tf32.tf32.f32 "
              "{%0,%1,%2,%3}, {%4,%5,%6,%7}, {%8,%9}, {%0,%1,%2,%3};"
              : "+f"(c[mt][nt][0]), "+f"(c[mt][nt][1]), "+f"(c[mt][nt][2]), "+f"(c[mt][nt][3])
              : "r"(a[mt][0]), "r"(a[mt][1]), "r"(a[mt][2]), "r"(a[mt][3]),
                "r"(b0[nt]), "r"(b1[nt]));
    }

    // epilogue: add bias, write out[b][o][t]
    int bb = ti >> 5;
    int t0 = (ti & 31) << 8;
    float* outb = out + (size_t)bb*O_*T_ + t0 + warp_n*64 + t4*2;
    #pragma unroll
    for (int mt = 0; mt < 2; ++mt) {
      int o0 = obase + mt*16, o1 = o0 + 8;
      float bv0 = sBias[o0], bv1 = sBias[o1];
      float* p0 = outb + (size_t)o0*T_;
      float* p1 = outb + (size_t)o1*T_;
      #pragma unroll
      for (int nt = 0; nt < 8; ++nt) {
        float2 v0 = make_float2(c[mt][nt][0]+bv0, c[mt][nt][1]+bv0);
        float2 v1 = make_float2(c[mt][nt][2]+bv1, c[mt][nt][3]+bv1);
        *reinterpret_cast<float2*>(p0 + nt*8) = v0;
        *reinterpret_cast<float2*>(p1 + nt*8) = v1;
      }
    }
    __syncthreads();
  }
}

// -------------------- launch --------------------
extern "C" void kernel_launch(void* const* d_in, const int* in_sizes, int n_in,
                              void* d_out, int out_size) {
  const float* x      = (const float*)d_in[0];
  const float* grads  = (const float*)d_in[1];
  const float* q_ema  = (const float*)d_in[2];
  const float* W      = (const float*)d_in[3];
  const float* conv_w = (const float*)d_in[4];
  const float* conv_b = (const float*)d_in[5];
  const float* ctrl_w = (const float*)d_in[6];
  const float* ctrl_b = (const float*)d_in[7];
  const float* cw_w   = (const float*)d_in[8];
  const float* cw_b   = (const float*)d_in[9];
  const float* cb_w   = (const float*)d_in[10];
  const float* cb_b   = (const float*)d_in[11];
  const float* cf_w   = (const float*)d_in[12];
  const float* cf_b   = (const float*)d_in[13];
  const float* tau_w1 = (const float*)d_in[14];
  const float* tau_b1 = (const float*)d_in[15];
  const float* tau_w2 = (const float*)d_in[16];
  const float* tau_b2 = (const float*)d_in[17];
  const int*   trig   = (const int*)d_in[18];
  float* out = (float*)d_out;

  prep_rep_kernel<<<64, 64>>>(grads, ctrl_w, ctrl_b);
  prep_q_kernel<<<1, 384>>>(q_ema, W, conv_w, conv_b, cw_w, cw_b, cb_w, cb_b,
                            cf_w, cf_b, tau_w1, tau_b1, tau_w2, tau_b2, trig);
  cudaFuncSetAttribute(conv_kernel, cudaFuncAttributeMaxDynamicSharedMemorySize, SMEM_BYTES);
  conv_kernel<<<CONV_GRID, CONV_THREADS, SMEM_BYTES>>>(x, out);
}